// round 15
// baseline (speedup 1.0000x reference)
#include <cuda_runtime.h>
#include <cuda_bf16.h>
#include <math.h>
#include <stdint.h>

#define SS   512
#define BB   64
#define HH   512
#define EE   512
#define MD   1024
#define NC   20
#define BH   (BB*HH)     // 32768
#define NROW (SS*BB)     // 32768
#define NCH  256         // s-pair chunks in phase C

// ---------------- scratch (static device memory; no allocs) ----------------
__device__ float g_emb[(size_t)NROW*EE];
__device__ float g_els[(size_t)NROW*HH];
__device__ float g_ers[(size_t)NROW*HH];
__device__ float g_cl [(size_t)NROW*HH];
__device__ float g_cr [(size_t)NROW*HH];
__device__ float g_part[(size_t)NCH*BB*MD];
__device__ __nv_bfloat16 g_whi[(size_t)MD*1536];    // Wmax hi
__device__ __nv_bfloat16 g_wlo[(size_t)MD*1536];    // Wmax lo
__device__ __nv_bfloat16 g_pwhi[(size_t)1024*512];  // [Wsl;Wsr] hi
__device__ __nv_bfloat16 g_pwlo[(size_t)1024*512];  // [Wsl;Wsr] lo

// ---------------- helpers ----------------------------------------------------
__device__ __forceinline__ uint32_t s2u(const void* p) {
    uint32_t a;
    asm("{ .reg .u64 t; cvta.to.shared.u64 t, %1; cvt.u32.u64 %0, t; }"
        : "=r"(a) : "l"(p));
    return a;
}
#define CLUSTER_SYNC() do { \
    asm volatile("barrier.cluster.arrive.aligned;" ::: "memory"); \
    asm volatile("barrier.cluster.wait.aligned;"   ::: "memory"); } while (0)

// ---------------- warp-MMA plumbing (sm_80+ instructions) -------------------
#define LDSM4(r, addr) \
    asm volatile("ldmatrix.sync.aligned.m8n8.x4.shared.b16 {%0,%1,%2,%3}, [%4];" \
        : "=r"((r)[0]), "=r"((r)[1]), "=r"((r)[2]), "=r"((r)[3]) : "r"(addr))
#define LDSM2(r, addr) \
    asm volatile("ldmatrix.sync.aligned.m8n8.x2.shared.b16 {%0,%1}, [%2];" \
        : "=r"((r)[0]), "=r"((r)[1]) : "r"(addr))
#define MMA_BF16(d, a, b) \
    asm volatile("mma.sync.aligned.m16n8k16.row.col.f32.bf16.bf16.f32 " \
        "{%0,%1,%2,%3}, {%4,%5,%6,%7}, {%8,%9}, {%0,%1,%2,%3};" \
        : "+f"((d)[0]), "+f"((d)[1]), "+f"((d)[2]), "+f"((d)[3]) \
        : "r"((a)[0]), "r"((a)[1]), "r"((a)[2]), "r"((a)[3]), \
          "r"((b)[0]), "r"((b)[1]))

// bf16 hi/lo split of a float pair (lo residual is exact in fp32)
__device__ __forceinline__ void split2(float x, float y, uint32_t& hi, uint32_t& lo) {
    __nv_bfloat162 h2 = __floats2bfloat162_rn(x, y);
    float hx = __bfloat162float(h2.x);
    float hy = __bfloat162float(h2.y);
    __nv_bfloat162 l2 = __floats2bfloat162_rn(x - hx, y - hy);
    hi = *(uint32_t*)&h2;
    lo = *(uint32_t*)&l2;
}

// shared tile geometry for both mma kernels
#define YM_PITCH 80
#define YM_MATB  (128*YM_PITCH)          // 10240
#define YM_AHI   0
#define YM_ALO   (YM_MATB)
#define YM_BHI   (2*YM_MATB)
#define YM_BLO   (3*YM_MATB)
#define YM_BUF   (4*YM_MATB)             // 40960
#define YM_SMEM  (2*YM_BUF)              // 81920

// ---------------- K0: embedding gather -------------------------------------
__global__ void gather_kernel(const int* __restrict__ inp,
                              const float* __restrict__ table) {
    int sb = blockIdx.x;
    int tok = inp[sb];
    const float4* src = reinterpret_cast<const float4*>(table + (size_t)tok * EE);
    float4* dst = reinterpret_cast<float4*>(g_emb + (size_t)sb * EE);
    dst[threadIdx.x] = src[threadIdx.x];
}

// ---------------- K0c: Wmax -> bf16 hi/lo -----------------------------------
__global__ void convw_kernel(const float* __restrict__ Wmax) {
    int m = blockIdx.x;
    for (int k = threadIdx.x; k < 1536; k += 256) {
        float x = Wmax[(size_t)m * 1536 + k];
        __nv_bfloat16 h = __float2bfloat16(x);
        float hf = __bfloat162float(h);
        g_whi[(size_t)m * 1536 + k] = h;
        g_wlo[(size_t)m * 1536 + k] = __float2bfloat16(x - hf);
    }
}

// ---------------- K0d: [Wsl;Wsr] -> bf16 hi/lo -------------------------------
__global__ void convp_kernel(const float* __restrict__ Wsl,
                             const float* __restrict__ Wsr) {
    int n = blockIdx.x;   // 0..1023
    const float* src = (n < 512) ? (Wsl + (size_t)n * 512)
                                 : (Wsr + (size_t)(n - 512) * 512);
    for (int k = threadIdx.x; k < 512; k += 256) {
        float x = src[k];
        __nv_bfloat16 h = __float2bfloat16(x);
        g_pwhi[(size_t)n * 512 + k] = h;
        g_pwlo[(size_t)n * 512 + k] = __float2bfloat16(x - __bfloat162float(h));
    }
}

// ---------------- K1: projection GEMM via mma.sync (hi/lo 3-term) -----------
// CTA tile 128 rows x 128 n-cols; K = 512 in 16 chunks of 32.
#define PR_CH 16

__global__ __launch_bounds__(256, 1)
void proj_kernel(const float* __restrict__ bsl, const float* __restrict__ bsr) {
    extern __shared__ char smb[];
    const uint32_t sbase = s2u(smb);
    const int t = threadIdx.x;
    const int lane = t & 31, wid = t >> 5;
    const int wr = wid & 3;
    const int wn = wid >> 2;
    const int n0 = blockIdx.x * 128;
    const int r0 = blockIdx.y * 128;
    const int frow = t >> 1, fhalf = t & 1;

    float acc[2][8][4];
    #pragma unroll
    for (int i = 0; i < 2; ++i)
        #pragma unroll
        for (int j = 0; j < 8; ++j)
            #pragma unroll
            for (int k = 0; k < 4; ++k) acc[i][j][k] = 0.f;

    auto fill_buf = [&](int bufi, int ch) {
        char* dst = smb + bufi * YM_BUF;
        const float* ap = g_emb + (size_t)(r0 + frow) * 512 + ch * 32 + fhalf * 16;
        float4 f0 = *(const float4*)(ap);
        float4 f1 = *(const float4*)(ap + 4);
        float4 f2 = *(const float4*)(ap + 8);
        float4 f3 = *(const float4*)(ap + 12);
        uint32_t hv[8], lv[8];
        split2(f0.x, f0.y, hv[0], lv[0]); split2(f0.z, f0.w, hv[1], lv[1]);
        split2(f1.x, f1.y, hv[2], lv[2]); split2(f1.z, f1.w, hv[3], lv[3]);
        split2(f2.x, f2.y, hv[4], lv[4]); split2(f2.z, f2.w, hv[5], lv[5]);
        split2(f3.x, f3.y, hv[6], lv[6]); split2(f3.z, f3.w, hv[7], lv[7]);
        const uint32_t off = (uint32_t)(frow * YM_PITCH + fhalf * 32);
        *(uint4*)(dst + YM_AHI + off)      = make_uint4(hv[0], hv[1], hv[2], hv[3]);
        *(uint4*)(dst + YM_AHI + off + 16) = make_uint4(hv[4], hv[5], hv[6], hv[7]);
        *(uint4*)(dst + YM_ALO + off)      = make_uint4(lv[0], lv[1], lv[2], lv[3]);
        *(uint4*)(dst + YM_ALO + off + 16) = make_uint4(lv[4], lv[5], lv[6], lv[7]);
        const __nv_bfloat16* bh = g_pwhi + (size_t)(n0 + frow) * 512 + ch * 32 + fhalf * 16;
        const __nv_bfloat16* bl = g_pwlo + (size_t)(n0 + frow) * 512 + ch * 32 + fhalf * 16;
        *(uint4*)(dst + YM_BHI + off)      = *(const uint4*)(bh);
        *(uint4*)(dst + YM_BHI + off + 16) = *(const uint4*)(bh + 8);
        *(uint4*)(dst + YM_BLO + off)      = *(const uint4*)(bl);
        *(uint4*)(dst + YM_BLO + off + 16) = *(const uint4*)(bl + 8);
    };

    fill_buf(0, 0);
    __syncthreads();

    int buf = 0;
    for (int c = 0; c < PR_CH; ++c) {
        const uint32_t sA = sbase + buf * YM_BUF;
        const uint32_t sB = sA + YM_BHI;
        #pragma unroll
        for (int ks = 0; ks < 2; ++ks) {
            uint32_t ah[2][4], al[2][4];
            #pragma unroll
            for (int mt = 0; mt < 2; ++mt) {
                uint32_t addr = sA + (uint32_t)((wr * 32 + mt * 16 + (lane & 15)) * YM_PITCH
                                                + ks * 32 + (lane >> 4) * 16);
                LDSM4(ah[mt], addr);
                LDSM4(al[mt], addr + YM_MATB);
            }
            uint32_t bh2[8][2], bl2[8][2];
            const int l = lane & 15;
            #pragma unroll
            for (int nt = 0; nt < 8; ++nt) {
                uint32_t addr = sB + (uint32_t)((wn * 64 + nt * 8 + (l & 7)) * YM_PITCH
                                                + ks * 32 + ((l >> 3) & 1) * 16);
                LDSM2(bh2[nt], addr);
                LDSM2(bl2[nt], addr + YM_MATB);
            }
            #pragma unroll
            for (int mt = 0; mt < 2; ++mt)
                #pragma unroll
                for (int nt = 0; nt < 8; ++nt) {
                    MMA_BF16(acc[mt][nt], ah[mt], bh2[nt]);
                    MMA_BF16(acc[mt][nt], ah[mt], bl2[nt]);
                    MMA_BF16(acc[mt][nt], al[mt], bh2[nt]);
                }
        }
        if (c + 1 < PR_CH) {
            fill_buf(buf ^ 1, c + 1);
            __syncthreads();
            buf ^= 1;
        }
    }

    // epilogue: bias add + direct stores to els/ers
    float* Out = (n0 < 512) ? g_els : g_ers;
    const float* bias = (n0 < 512) ? bsl : bsr;
    const int nb = n0 & 511;
    #pragma unroll
    for (int mt = 0; mt < 2; ++mt)
        #pragma unroll
        for (int nt = 0; nt < 8; ++nt) {
            int row = r0 + wr * 32 + mt * 16 + (lane >> 2);
            int col = wn * 64 + nt * 8 + ((lane & 3) << 1);
            float b0v = bias[nb + col];
            float b1v = bias[nb + col + 1];
            *(float2*)&Out[(size_t)row * 512 + nb + col] =
                make_float2(acc[mt][nt][0] + b0v, acc[mt][nt][1] + b1v);
            *(float2*)&Out[(size_t)(row + 8) * 512 + nb + col] =
                make_float2(acc[mt][nt][2] + b0v, acc[mt][nt][3] + b1v);
        }
}

// ---------------- K2: clustered bidirectional scan (unchanged) --------------
#define SCAN_W_FLT    (64*512)
#define SCAN_C_FLT    (512*8)
#define SCAN_P_FLT    (8*8*68)
#define SCAN_SMEM_FLT (SCAN_W_FLT + 2*SCAN_C_FLT + SCAN_P_FLT + 64)
#define SCAN_SMEM_BYTES (SCAN_SMEM_FLT*4)

__global__ void __cluster_dims__(8, 1, 1) __launch_bounds__(256, 1)
scan_kernel(const float* __restrict__ Wl, const float* __restrict__ bl,
            const float* __restrict__ Wr, const float* __restrict__ br,
            const float* __restrict__ cl0, const float* __restrict__ cr0) {
    extern __shared__ float sm[];
    float* Wsh  = sm;
    float* cshA = sm + SCAN_W_FLT;
    float* cshB = cshA + SCAN_C_FLT;
    float* part = cshB + SCAN_C_FLT;
    float* bsh  = part + SCAN_P_FLT;

    const int cid = blockIdx.x >> 3;
    const int rnk = blockIdx.x & 7;
    const int dir = cid & 1;
    const int b0  = (cid >> 1) * 8;
    const int j0  = rnk * 64;

    const float* W    = dir ? Wr  : Wl;
    const float* bias = dir ? br  : bl;
    const float* c0   = dir ? cr0 : cl0;
    const float* e    = dir ? g_ers : g_els;
    float* hist       = dir ? g_cr  : g_cl;

    const int t = threadIdx.x;
    for (int i = t; i < SCAN_W_FLT; i += 256) {
        int jl = i >> 9, k = i & 511;
        Wsh[k * 64 + jl] = W[(size_t)(j0 + jl) * 512 + k];
    }
    if (t < 64) bsh[t] = bias[j0 + t];
    for (int i = t; i < SCAN_C_FLT; i += 256)
        cshA[i] = c0[i >> 3];
    __syncthreads();
    CLUSTER_SYNC();

    const int kg = t >> 5;
    const int jq = t & 15;
    const int bq = (t >> 4) & 1;
    const int kbase = kg * 64;
    const int bi1 = t >> 6,          jl1 = t & 63;
    const int bi2 = (t + 256) >> 6,  jl2 = t & 63;

    float* cur = cshA;
    float* nxt = cshB;

    for (int step = 0; step < SS; ++step) {
        const int s = dir ? (SS - 1 - step) : step;
        const size_t ebase = (size_t)s * BH;
        float e1 = __ldcg(&e[ebase + (size_t)(b0 + bi1) * 512 + j0 + jl1]);
        float e2 = __ldcg(&e[ebase + (size_t)(b0 + bi2) * 512 + j0 + jl2]);

        float acc[4][4];
        #pragma unroll
        for (int i = 0; i < 4; ++i)
            #pragma unroll
            for (int j = 0; j < 4; ++j) acc[i][j] = 0.f;

        const float* cp = cur + (size_t)kbase * 8 + bq * 4;
        const float* wp = Wsh + (size_t)kbase * 64 + jq * 4;
        #pragma unroll 8
        for (int k = 0; k < 64; ++k) {
            float4 c4 = *(const float4*)(cp + k * 8);
            float4 w4 = *(const float4*)(wp + k * 64);
            acc[0][0] += c4.x*w4.x; acc[0][1] += c4.x*w4.y; acc[0][2] += c4.x*w4.z; acc[0][3] += c4.x*w4.w;
            acc[1][0] += c4.y*w4.x; acc[1][1] += c4.y*w4.y; acc[1][2] += c4.y*w4.z; acc[1][3] += c4.y*w4.w;
            acc[2][0] += c4.z*w4.x; acc[2][1] += c4.z*w4.y; acc[2][2] += c4.z*w4.z; acc[2][3] += c4.z*w4.w;
            acc[3][0] += c4.w*w4.x; acc[3][1] += c4.w*w4.y; acc[3][2] += c4.w*w4.z; acc[3][3] += c4.w*w4.w;
        }
        #pragma unroll
        for (int bb = 0; bb < 4; ++bb) {
            int b = bq * 4 + bb;
            *(float4*)&part[(kg * 8 + b) * 68 + jq * 4] =
                make_float4(acc[bb][0], acc[bb][1], acc[bb][2], acc[bb][3]);
        }
        __syncthreads();

        const uint32_t nxt_u = s2u(nxt);
        #pragma unroll
        for (int h = 0; h < 2; ++h) {
            const int bi = h ? bi2 : bi1;
            const int jl = h ? jl2 : jl1;
            float v = 0.f;
            #pragma unroll
            for (int g = 0; g < 8; ++g) v += part[(g * 8 + bi) * 68 + jl];
            v = tanhf(v + bsh[jl] + (h ? e2 : e1));
            hist[ebase + (size_t)(b0 + bi) * 512 + j0 + jl] = v;
            const uint32_t loc = nxt_u + (uint32_t)(((j0 + jl) * 8 + bi) * 4);
            const uint32_t vv  = __float_as_uint(v);
            #pragma unroll
            for (int rr = 0; rr < 8; ++rr) {
                uint32_t rem;
                asm("mapa.shared::cluster.u32 %0, %1, %2;" : "=r"(rem) : "r"(loc), "r"(rr));
                asm volatile("st.shared::cluster.b32 [%0], %1;" :: "r"(rem), "r"(vv) : "memory");
            }
        }
        CLUSTER_SYNC();
        float* tmp = cur; cur = nxt; nxt = tmp;
    }
}

// ---------------- K3: ymax via warp-level bf16 mma.sync (unchanged) ---------
#define YM_CH    48

__global__ __launch_bounds__(256, 1)
void ymax_kernel() {
    extern __shared__ char smb[];
    const uint32_t sbase = s2u(smb);
    const int t = threadIdx.x;
    const int lane = t & 31, wid = t >> 5;
    const int wr = wid & 3;
    const int wn = wid >> 2;
    const int m0 = blockIdx.x * 128;
    const int r0 = blockIdx.y * 128;
    const int frow = t >> 1, fhalf = t & 1;

    float acc[2][8][4];
    #pragma unroll
    for (int i = 0; i < 2; ++i)
        #pragma unroll
        for (int j = 0; j < 8; ++j)
            #pragma unroll
            for (int k = 0; k < 4; ++k) acc[i][j][k] = 0.f;

    auto fill_buf = [&](int bufi, int ch) {
        char* dst = smb + bufi * YM_BUF;
        const float* Asrc = (ch < 16) ? g_cl : (ch < 32) ? g_emb : g_cr;
        const float* ap = Asrc + (size_t)(r0 + frow) * 512 + (ch & 15) * 32 + fhalf * 16;
        float4 f0 = *(const float4*)(ap);
        float4 f1 = *(const float4*)(ap + 4);
        float4 f2 = *(const float4*)(ap + 8);
        float4 f3 = *(const float4*)(ap + 12);
        uint32_t hv[8], lv[8];
        split2(f0.x, f0.y, hv[0], lv[0]); split2(f0.z, f0.w, hv[1], lv[1]);
        split2(f1.x, f1.y, hv[2], lv[2]); split2(f1.z, f1.w, hv[3], lv[3]);
        split2(f2.x, f2.y, hv[4], lv[4]); split2(f2.z, f2.w, hv[5], lv[5]);
        split2(f3.x, f3.y, hv[6], lv[6]); split2(f3.z, f3.w, hv[7], lv[7]);
        const uint32_t off = (uint32_t)(frow * YM_PITCH + fhalf * 32);
        *(uint4*)(dst + YM_AHI + off)      = make_uint4(hv[0], hv[1], hv[2], hv[3]);
        *(uint4*)(dst + YM_AHI + off + 16) = make_uint4(hv[4], hv[5], hv[6], hv[7]);
        *(uint4*)(dst + YM_ALO + off)      = make_uint4(lv[0], lv[1], lv[2], lv[3]);
        *(uint4*)(dst + YM_ALO + off + 16) = make_uint4(lv[4], lv[5], lv[6], lv[7]);
        const __nv_bfloat16* bh = g_whi + (size_t)(m0 + frow) * 1536 + ch * 32 + fhalf * 16;
        const __nv_bfloat16* bl = g_wlo + (size_t)(m0 + frow) * 1536 + ch * 32 + fhalf * 16;
        *(uint4*)(dst + YM_BHI + off)      = *(const uint4*)(bh);
        *(uint4*)(dst + YM_BHI + off + 16) = *(const uint4*)(bh + 8);
        *(uint4*)(dst + YM_BLO + off)      = *(const uint4*)(bl);
        *(uint4*)(dst + YM_BLO + off + 16) = *(const uint4*)(bl + 8);
    };

    fill_buf(0, 0);
    __syncthreads();

    int buf = 0;
    for (int c = 0; c < YM_CH; ++c) {
        const uint32_t sA = sbase + buf * YM_BUF;
        const uint32_t sB = sA + YM_BHI;
        #pragma unroll
        for (int ks = 0; ks < 2; ++ks) {
            uint32_t ah[2][4], al[2][4];
            #pragma unroll
            for (int mt = 0; mt < 2; ++mt) {
                uint32_t addr = sA + (uint32_t)((wr * 32 + mt * 16 + (lane & 15)) * YM_PITCH
                                                + ks * 32 + (lane >> 4) * 16);
                LDSM4(ah[mt], addr);
                LDSM4(al[mt], addr + YM_MATB);
            }
            uint32_t bh2[8][2], bl2[8][2];
            const int l = lane & 15;
            #pragma unroll
            for (int nt = 0; nt < 8; ++nt) {
                uint32_t addr = sB + (uint32_t)((wn * 64 + nt * 8 + (l & 7)) * YM_PITCH
                                                + ks * 32 + ((l >> 3) & 1) * 16);
                LDSM2(bh2[nt], addr);
                LDSM2(bl2[nt], addr + YM_MATB);
            }
            #pragma unroll
            for (int mt = 0; mt < 2; ++mt)
                #pragma unroll
                for (int nt = 0; nt < 8; ++nt) {
                    MMA_BF16(acc[mt][nt], ah[mt], bh2[nt]);
                    MMA_BF16(acc[mt][nt], ah[mt], bl2[nt]);
                    MMA_BF16(acc[mt][nt], al[mt], bh2[nt]);
                }
        }
        if (c + 1 < YM_CH) {
            fill_buf(buf ^ 1, c + 1);
            __syncthreads();
            buf ^= 1;
        }
    }
    __syncthreads();

    float* Dsm = (float*)smb;            // [128][132]
    #pragma unroll
    for (int mt = 0; mt < 2; ++mt)
        #pragma unroll
        for (int nt = 0; nt < 8; ++nt) {
            int row = wr * 32 + mt * 16 + (lane >> 2);
            int col = wn * 64 + nt * 8 + ((lane & 3) << 1);
            *(float2*)&Dsm[row * 132 + col]       = make_float2(acc[mt][nt][0], acc[mt][nt][1]);
            *(float2*)&Dsm[(row + 8) * 132 + col] = make_float2(acc[mt][nt][2], acc[mt][nt][3]);
        }
    __syncthreads();
    {
        const size_t chb = ((size_t)blockIdx.y * BB) * MD;
        #pragma unroll
        for (int i = 0; i < 8; ++i) {
            int idx = t + i * 256;
            int b = idx & 63;
            int q = idx >> 6;
            int c0 = q * 4;
            float4 v0 = *(float4*)&Dsm[b * 132 + c0];
            float4 v1 = *(float4*)&Dsm[(b + 64) * 132 + c0];
            float4 o = make_float4(fmaxf(v0.x, v1.x), fmaxf(v0.y, v1.y),
                                   fmaxf(v0.z, v1.z), fmaxf(v0.w, v1.w));
            *(float4*)&g_part[chb + (size_t)b * MD + m0 + c0] = o;
        }
    }
}

// ---------------- K4: final reduce + tanh + logits + log_softmax ------------
__global__ void head_kernel(const float* __restrict__ bmax,
                            const float* __restrict__ Wdoc,
                            const float* __restrict__ bdoc,
                            float* __restrict__ out) {
    __shared__ float ysh[MD];
    __shared__ float lsh[NC];
    const int b = blockIdx.x;
    const int t = threadIdx.x;
    for (int m = t; m < MD; m += 256) {
        float v = -3.402823466e38f;
        for (int ch = 0; ch < NCH; ++ch)
            v = fmaxf(v, g_part[((size_t)ch * BB + b) * MD + m]);
        ysh[m] = tanhf(v + bmax[m]);
    }
    __syncthreads();
    const int w = t >> 5, lane = t & 31;
    for (int c = w; c < NC; c += 8) {
        float sum = 0.f;
        for (int m = lane; m < MD; m += 32)
            sum += ysh[m] * Wdoc[(size_t)c * MD + m];
        #pragma unroll
        for (int off = 16; off; off >>= 1)
            sum += __shfl_down_sync(0xffffffffu, sum, off);
        if (lane == 0) lsh[c] = sum + bdoc[c];
    }
    __syncthreads();
    if (t == 0) {
        float mx = lsh[0];
        for (int c = 1; c < NC; ++c) mx = fmaxf(mx, lsh[c]);
        float se = 0.f;
        for (int c = 0; c < NC; ++c) se += expf(lsh[c] - mx);
        float lse = logf(se) + mx;
        for (int c = 0; c < NC; ++c) out[b * NC + c] = lsh[c] - lse;
    }
}

// ---------------- launch -----------------------------------------------------
extern "C" void kernel_launch(void* const* d_in, const int* in_sizes, int n_in,
                              void* d_out, int out_size) {
    const int*   inp   = (const int*)  d_in[0];
    const float* table = (const float*)d_in[1];
    const float* cl0   = (const float*)d_in[2];
    const float* cr0   = (const float*)d_in[3];
    const float* Wl    = (const float*)d_in[4];
    const float* bl    = (const float*)d_in[5];
    const float* Wr    = (const float*)d_in[6];
    const float* br    = (const float*)d_in[7];
    const float* Wsl   = (const float*)d_in[8];
    const float* bsl   = (const float*)d_in[9];
    const float* Wsr   = (const float*)d_in[10];
    const float* bsr   = (const float*)d_in[11];
    const float* Wmax  = (const float*)d_in[12];
    const float* bmax  = (const float*)d_in[13];
    const float* Wdoc  = (const float*)d_in[14];
    const float* bdoc  = (const float*)d_in[15];
    float* out = (float*)d_out;

    cudaFuncSetAttribute(scan_kernel,
                         cudaFuncAttributeMaxDynamicSharedMemorySize,
                         SCAN_SMEM_BYTES);
    cudaFuncSetAttribute(ymax_kernel,
                         cudaFuncAttributeMaxDynamicSharedMemorySize,
                         YM_SMEM);
    cudaFuncSetAttribute(proj_kernel,
                         cudaFuncAttributeMaxDynamicSharedMemorySize,
                         YM_SMEM);

    gather_kernel<<<NROW, 128>>>(inp, table);
    convw_kernel<<<MD, 256>>>(Wmax);
    convp_kernel<<<1024, 256>>>(Wsl, Wsr);
    proj_kernel<<<dim3(1024 / 128, NROW / 128), 256, YM_SMEM>>>(bsl, bsr);
    scan_kernel<<<128, 256, SCAN_SMEM_BYTES>>>(Wl, bl, Wr, br, cl0, cr0);
    ymax_kernel<<<dim3(MD / 128, NCH), 256, YM_SMEM>>>();
    head_kernel<<<BB, 256>>>(bmax, Wdoc, bdoc, out);
}

// round 16
// speedup vs baseline: 1.0726x; 1.0726x over previous
#include <cuda_runtime.h>
#include <cuda_bf16.h>
#include <math.h>
#include <stdint.h>

#define SS   512
#define BB   64
#define HH   512
#define EE   512
#define MD   1024
#define NC   20
#define BH   (BB*HH)     // 32768
#define NROW (SS*BB)     // 32768
#define NCH  256         // s-pair chunks in phase C

// ---------------- scratch (static device memory; no allocs) ----------------
__device__ float g_emb[(size_t)NROW*EE];
__device__ float g_els[(size_t)NROW*HH];
__device__ float g_ers[(size_t)NROW*HH];
__device__ float g_cl [(size_t)NROW*HH];
__device__ float g_cr [(size_t)NROW*HH];
__device__ float g_part[(size_t)NCH*BB*MD];
__device__ __nv_bfloat16 g_whi[(size_t)MD*1536];    // Wmax hi
__device__ __nv_bfloat16 g_wlo[(size_t)MD*1536];    // Wmax lo
__device__ __nv_bfloat16 g_pwhi[(size_t)1024*512];  // [Wsl;Wsr] hi
__device__ __nv_bfloat16 g_pwlo[(size_t)1024*512];  // [Wsl;Wsr] lo

// ---------------- helpers ----------------------------------------------------
__device__ __forceinline__ uint32_t s2u(const void* p) {
    uint32_t a;
    asm("{ .reg .u64 t; cvta.to.shared.u64 t, %1; cvt.u32.u64 %0, t; }"
        : "=r"(a) : "l"(p));
    return a;
}
#define CLUSTER_SYNC() do { \
    asm volatile("barrier.cluster.arrive.aligned;" ::: "memory"); \
    asm volatile("barrier.cluster.wait.aligned;"   ::: "memory"); } while (0)

// ---------------- warp-MMA plumbing (sm_80+ instructions) -------------------
#define LDSM4(r, addr) \
    asm volatile("ldmatrix.sync.aligned.m8n8.x4.shared.b16 {%0,%1,%2,%3}, [%4];" \
        : "=r"((r)[0]), "=r"((r)[1]), "=r"((r)[2]), "=r"((r)[3]) : "r"(addr))
#define LDSM2(r, addr) \
    asm volatile("ldmatrix.sync.aligned.m8n8.x2.shared.b16 {%0,%1}, [%2];" \
        : "=r"((r)[0]), "=r"((r)[1]) : "r"(addr))
#define MMA_BF16(d, a, b) \
    asm volatile("mma.sync.aligned.m16n8k16.row.col.f32.bf16.bf16.f32 " \
        "{%0,%1,%2,%3}, {%4,%5,%6,%7}, {%8,%9}, {%0,%1,%2,%3};" \
        : "+f"((d)[0]), "+f"((d)[1]), "+f"((d)[2]), "+f"((d)[3]) \
        : "r"((a)[0]), "r"((a)[1]), "r"((a)[2]), "r"((a)[3]), \
          "r"((b)[0]), "r"((b)[1]))

// bf16 hi/lo split of a float pair (lo residual is exact in fp32)
__device__ __forceinline__ void split2(float x, float y, uint32_t& hi, uint32_t& lo) {
    __nv_bfloat162 h2 = __floats2bfloat162_rn(x, y);
    float hx = __bfloat162float(h2.x);
    float hy = __bfloat162float(h2.y);
    __nv_bfloat162 l2 = __floats2bfloat162_rn(x - hx, y - hy);
    hi = *(uint32_t*)&h2;
    lo = *(uint32_t*)&l2;
}

// shared tile geometry for both mma kernels
#define YM_PITCH 80
#define YM_MATB  (128*YM_PITCH)          // 10240
#define YM_AHI   0
#define YM_ALO   (YM_MATB)
#define YM_BHI   (2*YM_MATB)
#define YM_BLO   (3*YM_MATB)
#define YM_BUF   (4*YM_MATB)             // 40960
#define YM_SMEM  (2*YM_BUF)              // 81920 ; x2 CTAs = 160KB <= 228KB

// ---------------- K0: embedding gather -------------------------------------
__global__ void gather_kernel(const int* __restrict__ inp,
                              const float* __restrict__ table) {
    int sb = blockIdx.x;
    int tok = inp[sb];
    const float4* src = reinterpret_cast<const float4*>(table + (size_t)tok * EE);
    float4* dst = reinterpret_cast<float4*>(g_emb + (size_t)sb * EE);
    dst[threadIdx.x] = src[threadIdx.x];
}

// ---------------- K0c: Wmax -> bf16 hi/lo -----------------------------------
__global__ void convw_kernel(const float* __restrict__ Wmax) {
    int m = blockIdx.x;
    for (int k = threadIdx.x; k < 1536; k += 256) {
        float x = Wmax[(size_t)m * 1536 + k];
        __nv_bfloat16 h = __float2bfloat16(x);
        float hf = __bfloat162float(h);
        g_whi[(size_t)m * 1536 + k] = h;
        g_wlo[(size_t)m * 1536 + k] = __float2bfloat16(x - hf);
    }
}

// ---------------- K0d: [Wsl;Wsr] -> bf16 hi/lo -------------------------------
__global__ void convp_kernel(const float* __restrict__ Wsl,
                             const float* __restrict__ Wsr) {
    int n = blockIdx.x;   // 0..1023
    const float* src = (n < 512) ? (Wsl + (size_t)n * 512)
                                 : (Wsr + (size_t)(n - 512) * 512);
    for (int k = threadIdx.x; k < 512; k += 256) {
        float x = src[k];
        __nv_bfloat16 h = __float2bfloat16(x);
        g_pwhi[(size_t)n * 512 + k] = h;
        g_pwlo[(size_t)n * 512 + k] = __float2bfloat16(x - __bfloat162float(h));
    }
}

// ---------------- K1: projection GEMM via mma.sync (hi/lo 3-term) -----------
// CTA tile 128 rows x 128 n-cols; K = 512 in 16 chunks of 32; occupancy 2.
#define PR_CH 16

__global__ __launch_bounds__(256, 2)
void proj_kernel(const float* __restrict__ bsl, const float* __restrict__ bsr) {
    extern __shared__ char smb[];
    const uint32_t sbase = s2u(smb);
    const int t = threadIdx.x;
    const int lane = t & 31, wid = t >> 5;
    const int wr = wid & 3;
    const int wn = wid >> 2;
    const int n0 = blockIdx.x * 128;
    const int r0 = blockIdx.y * 128;
    const int frow = t >> 1, fhalf = t & 1;

    float acc[2][8][4];
    #pragma unroll
    for (int i = 0; i < 2; ++i)
        #pragma unroll
        for (int j = 0; j < 8; ++j)
            #pragma unroll
            for (int k = 0; k < 4; ++k) acc[i][j][k] = 0.f;

    auto fill_buf = [&](int bufi, int ch) {
        char* dst = smb + bufi * YM_BUF;
        const float* ap = g_emb + (size_t)(r0 + frow) * 512 + ch * 32 + fhalf * 16;
        float4 f0 = *(const float4*)(ap);
        float4 f1 = *(const float4*)(ap + 4);
        float4 f2 = *(const float4*)(ap + 8);
        float4 f3 = *(const float4*)(ap + 12);
        uint32_t hv[8], lv[8];
        split2(f0.x, f0.y, hv[0], lv[0]); split2(f0.z, f0.w, hv[1], lv[1]);
        split2(f1.x, f1.y, hv[2], lv[2]); split2(f1.z, f1.w, hv[3], lv[3]);
        split2(f2.x, f2.y, hv[4], lv[4]); split2(f2.z, f2.w, hv[5], lv[5]);
        split2(f3.x, f3.y, hv[6], lv[6]); split2(f3.z, f3.w, hv[7], lv[7]);
        const uint32_t off = (uint32_t)(frow * YM_PITCH + fhalf * 32);
        *(uint4*)(dst + YM_AHI + off)      = make_uint4(hv[0], hv[1], hv[2], hv[3]);
        *(uint4*)(dst + YM_AHI + off + 16) = make_uint4(hv[4], hv[5], hv[6], hv[7]);
        *(uint4*)(dst + YM_ALO + off)      = make_uint4(lv[0], lv[1], lv[2], lv[3]);
        *(uint4*)(dst + YM_ALO + off + 16) = make_uint4(lv[4], lv[5], lv[6], lv[7]);
        const __nv_bfloat16* bh = g_pwhi + (size_t)(n0 + frow) * 512 + ch * 32 + fhalf * 16;
        const __nv_bfloat16* bl = g_pwlo + (size_t)(n0 + frow) * 512 + ch * 32 + fhalf * 16;
        *(uint4*)(dst + YM_BHI + off)      = *(const uint4*)(bh);
        *(uint4*)(dst + YM_BHI + off + 16) = *(const uint4*)(bh + 8);
        *(uint4*)(dst + YM_BLO + off)      = *(const uint4*)(bl);
        *(uint4*)(dst + YM_BLO + off + 16) = *(const uint4*)(bl + 8);
    };

    fill_buf(0, 0);
    __syncthreads();

    int buf = 0;
    for (int c = 0; c < PR_CH; ++c) {
        const uint32_t sA = sbase + buf * YM_BUF;
        const uint32_t sB = sA + YM_BHI;
        #pragma unroll
        for (int ks = 0; ks < 2; ++ks) {
            uint32_t ah[2][4], al[2][4];
            #pragma unroll
            for (int mt = 0; mt < 2; ++mt) {
                uint32_t addr = sA + (uint32_t)((wr * 32 + mt * 16 + (lane & 15)) * YM_PITCH
                                                + ks * 32 + (lane >> 4) * 16);
                LDSM4(ah[mt], addr);
                LDSM4(al[mt], addr + YM_MATB);
            }
            uint32_t bh2[8][2], bl2[8][2];
            const int l = lane & 15;
            #pragma unroll
            for (int nt = 0; nt < 8; ++nt) {
                uint32_t addr = sB + (uint32_t)((wn * 64 + nt * 8 + (l & 7)) * YM_PITCH
                                                + ks * 32 + ((l >> 3) & 1) * 16);
                LDSM2(bh2[nt], addr);
                LDSM2(bl2[nt], addr + YM_MATB);
            }
            #pragma unroll
            for (int mt = 0; mt < 2; ++mt)
                #pragma unroll
                for (int nt = 0; nt < 8; ++nt) {
                    MMA_BF16(acc[mt][nt], ah[mt], bh2[nt]);
                    MMA_BF16(acc[mt][nt], ah[mt], bl2[nt]);
                    MMA_BF16(acc[mt][nt], al[mt], bh2[nt]);
                }
        }
        if (c + 1 < PR_CH) {
            fill_buf(buf ^ 1, c + 1);
            __syncthreads();
            buf ^= 1;
        }
    }

    // epilogue: bias add + direct stores to els/ers
    float* Out = (n0 < 512) ? g_els : g_ers;
    const float* bias = (n0 < 512) ? bsl : bsr;
    const int nb = n0 & 511;
    #pragma unroll
    for (int mt = 0; mt < 2; ++mt)
        #pragma unroll
        for (int nt = 0; nt < 8; ++nt) {
            int row = r0 + wr * 32 + mt * 16 + (lane >> 2);
            int col = wn * 64 + nt * 8 + ((lane & 3) << 1);
            float b0v = bias[nb + col];
            float b1v = bias[nb + col + 1];
            *(float2*)&Out[(size_t)row * 512 + nb + col] =
                make_float2(acc[mt][nt][0] + b0v, acc[mt][nt][1] + b1v);
            *(float2*)&Out[(size_t)(row + 8) * 512 + nb + col] =
                make_float2(acc[mt][nt][2] + b0v, acc[mt][nt][3] + b1v);
        }
}

// ---------------- K2: clustered bidirectional scan (unchanged) --------------
#define SCAN_W_FLT    (64*512)
#define SCAN_C_FLT    (512*8)
#define SCAN_P_FLT    (8*8*68)
#define SCAN_SMEM_FLT (SCAN_W_FLT + 2*SCAN_C_FLT + SCAN_P_FLT + 64)
#define SCAN_SMEM_BYTES (SCAN_SMEM_FLT*4)

__global__ void __cluster_dims__(8, 1, 1) __launch_bounds__(256, 1)
scan_kernel(const float* __restrict__ Wl, const float* __restrict__ bl,
            const float* __restrict__ Wr, const float* __restrict__ br,
            const float* __restrict__ cl0, const float* __restrict__ cr0) {
    extern __shared__ float sm[];
    float* Wsh  = sm;
    float* cshA = sm + SCAN_W_FLT;
    float* cshB = cshA + SCAN_C_FLT;
    float* part = cshB + SCAN_C_FLT;
    float* bsh  = part + SCAN_P_FLT;

    const int cid = blockIdx.x >> 3;
    const int rnk = blockIdx.x & 7;
    const int dir = cid & 1;
    const int b0  = (cid >> 1) * 8;
    const int j0  = rnk * 64;

    const float* W    = dir ? Wr  : Wl;
    const float* bias = dir ? br  : bl;
    const float* c0   = dir ? cr0 : cl0;
    const float* e    = dir ? g_ers : g_els;
    float* hist       = dir ? g_cr  : g_cl;

    const int t = threadIdx.x;
    for (int i = t; i < SCAN_W_FLT; i += 256) {
        int jl = i >> 9, k = i & 511;
        Wsh[k * 64 + jl] = W[(size_t)(j0 + jl) * 512 + k];
    }
    if (t < 64) bsh[t] = bias[j0 + t];
    for (int i = t; i < SCAN_C_FLT; i += 256)
        cshA[i] = c0[i >> 3];
    __syncthreads();
    CLUSTER_SYNC();

    const int kg = t >> 5;
    const int jq = t & 15;
    const int bq = (t >> 4) & 1;
    const int kbase = kg * 64;
    const int bi1 = t >> 6,          jl1 = t & 63;
    const int bi2 = (t + 256) >> 6,  jl2 = t & 63;

    float* cur = cshA;
    float* nxt = cshB;

    for (int step = 0; step < SS; ++step) {
        const int s = dir ? (SS - 1 - step) : step;
        const size_t ebase = (size_t)s * BH;
        float e1 = __ldcg(&e[ebase + (size_t)(b0 + bi1) * 512 + j0 + jl1]);
        float e2 = __ldcg(&e[ebase + (size_t)(b0 + bi2) * 512 + j0 + jl2]);

        float acc[4][4];
        #pragma unroll
        for (int i = 0; i < 4; ++i)
            #pragma unroll
            for (int j = 0; j < 4; ++j) acc[i][j] = 0.f;

        const float* cp = cur + (size_t)kbase * 8 + bq * 4;
        const float* wp = Wsh + (size_t)kbase * 64 + jq * 4;
        #pragma unroll 8
        for (int k = 0; k < 64; ++k) {
            float4 c4 = *(const float4*)(cp + k * 8);
            float4 w4 = *(const float4*)(wp + k * 64);
            acc[0][0] += c4.x*w4.x; acc[0][1] += c4.x*w4.y; acc[0][2] += c4.x*w4.z; acc[0][3] += c4.x*w4.w;
            acc[1][0] += c4.y*w4.x; acc[1][1] += c4.y*w4.y; acc[1][2] += c4.y*w4.z; acc[1][3] += c4.y*w4.w;
            acc[2][0] += c4.z*w4.x; acc[2][1] += c4.z*w4.y; acc[2][2] += c4.z*w4.z; acc[2][3] += c4.z*w4.w;
            acc[3][0] += c4.w*w4.x; acc[3][1] += c4.w*w4.y; acc[3][2] += c4.w*w4.z; acc[3][3] += c4.w*w4.w;
        }
        #pragma unroll
        for (int bb = 0; bb < 4; ++bb) {
            int b = bq * 4 + bb;
            *(float4*)&part[(kg * 8 + b) * 68 + jq * 4] =
                make_float4(acc[bb][0], acc[bb][1], acc[bb][2], acc[bb][3]);
        }
        __syncthreads();

        const uint32_t nxt_u = s2u(nxt);
        #pragma unroll
        for (int h = 0; h < 2; ++h) {
            const int bi = h ? bi2 : bi1;
            const int jl = h ? jl2 : jl1;
            float v = 0.f;
            #pragma unroll
            for (int g = 0; g < 8; ++g) v += part[(g * 8 + bi) * 68 + jl];
            v = tanhf(v + bsh[jl] + (h ? e2 : e1));
            hist[ebase + (size_t)(b0 + bi) * 512 + j0 + jl] = v;
            const uint32_t loc = nxt_u + (uint32_t)(((j0 + jl) * 8 + bi) * 4);
            const uint32_t vv  = __float_as_uint(v);
            #pragma unroll
            for (int rr = 0; rr < 8; ++rr) {
                uint32_t rem;
                asm("mapa.shared::cluster.u32 %0, %1, %2;" : "=r"(rem) : "r"(loc), "r"(rr));
                asm volatile("st.shared::cluster.b32 [%0], %1;" :: "r"(rem), "r"(vv) : "memory");
            }
        }
        CLUSTER_SYNC();
        float* tmp = cur; cur = nxt; nxt = tmp;
    }
}

// ---------------- K3: ymax via warp-level bf16 mma.sync; occupancy 2 --------
#define YM_CH    48

__global__ __launch_bounds__(256, 2)
void ymax_kernel() {
    extern __shared__ char smb[];
    const uint32_t sbase = s2u(smb);
    const int t = threadIdx.x;
    const int lane = t & 31, wid = t >> 5;
    const int wr = wid & 3;
    const int wn = wid >> 2;
    const int m0 = blockIdx.x * 128;
    const int r0 = blockIdx.y * 128;
    const int frow = t >> 1, fhalf = t & 1;

    float acc[2][8][4];
    #pragma unroll
    for (int i = 0; i < 2; ++i)
        #pragma unroll
        for (int j = 0; j < 8; ++j)
            #pragma unroll
            for (int k = 0; k < 4; ++k) acc[i][j][k] = 0.f;

    auto fill_buf = [&](int bufi, int ch) {
        char* dst = smb + bufi * YM_BUF;
        const float* Asrc = (ch < 16) ? g_cl : (ch < 32) ? g_emb : g_cr;
        const float* ap = Asrc + (size_t)(r0 + frow) * 512 + (ch & 15) * 32 + fhalf * 16;
        float4 f0 = *(const float4*)(ap);
        float4 f1 = *(const float4*)(ap + 4);
        float4 f2 = *(const float4*)(ap + 8);
        float4 f3 = *(const float4*)(ap + 12);
        uint32_t hv[8], lv[8];
        split2(f0.x, f0.y, hv[0], lv[0]); split2(f0.z, f0.w, hv[1], lv[1]);
        split2(f1.x, f1.y, hv[2], lv[2]); split2(f1.z, f1.w, hv[3], lv[3]);
        split2(f2.x, f2.y, hv[4], lv[4]); split2(f2.z, f2.w, hv[5], lv[5]);
        split2(f3.x, f3.y, hv[6], lv[6]); split2(f3.z, f3.w, hv[7], lv[7]);
        const uint32_t off = (uint32_t)(frow * YM_PITCH + fhalf * 32);
        *(uint4*)(dst + YM_AHI + off)      = make_uint4(hv[0], hv[1], hv[2], hv[3]);
        *(uint4*)(dst + YM_AHI + off + 16) = make_uint4(hv[4], hv[5], hv[6], hv[7]);
        *(uint4*)(dst + YM_ALO + off)      = make_uint4(lv[0], lv[1], lv[2], lv[3]);
        *(uint4*)(dst + YM_ALO + off + 16) = make_uint4(lv[4], lv[5], lv[6], lv[7]);
        const __nv_bfloat16* bh = g_whi + (size_t)(m0 + frow) * 1536 + ch * 32 + fhalf * 16;
        const __nv_bfloat16* bl = g_wlo + (size_t)(m0 + frow) * 1536 + ch * 32 + fhalf * 16;
        *(uint4*)(dst + YM_BHI + off)      = *(const uint4*)(bh);
        *(uint4*)(dst + YM_BHI + off + 16) = *(const uint4*)(bh + 8);
        *(uint4*)(dst + YM_BLO + off)      = *(const uint4*)(bl);
        *(uint4*)(dst + YM_BLO + off + 16) = *(const uint4*)(bl + 8);
    };

    fill_buf(0, 0);
    __syncthreads();

    int buf = 0;
    for (int c = 0; c < YM_CH; ++c) {
        const uint32_t sA = sbase + buf * YM_BUF;
        const uint32_t sB = sA + YM_BHI;
        #pragma unroll
        for (int ks = 0; ks < 2; ++ks) {
            uint32_t ah[2][4], al[2][4];
            #pragma unroll
            for (int mt = 0; mt < 2; ++mt) {
                uint32_t addr = sA + (uint32_t)((wr * 32 + mt * 16 + (lane & 15)) * YM_PITCH
                                                + ks * 32 + (lane >> 4) * 16);
                LDSM4(ah[mt], addr);
                LDSM4(al[mt], addr + YM_MATB);
            }
            uint32_t bh2[8][2], bl2[8][2];
            const int l = lane & 15;
            #pragma unroll
            for (int nt = 0; nt < 8; ++nt) {
                uint32_t addr = sB + (uint32_t)((wn * 64 + nt * 8 + (l & 7)) * YM_PITCH
                                                + ks * 32 + ((l >> 3) & 1) * 16);
                LDSM2(bh2[nt], addr);
                LDSM2(bl2[nt], addr + YM_MATB);
            }
            #pragma unroll
            for (int mt = 0; mt < 2; ++mt)
                #pragma unroll
                for (int nt = 0; nt < 8; ++nt) {
                    MMA_BF16(acc[mt][nt], ah[mt], bh2[nt]);
                    MMA_BF16(acc[mt][nt], ah[mt], bl2[nt]);
                    MMA_BF16(acc[mt][nt], al[mt], bh2[nt]);
                }
        }
        if (c + 1 < YM_CH) {
            fill_buf(buf ^ 1, c + 1);
            __syncthreads();
            buf ^= 1;
        }
    }
    __syncthreads();

    float* Dsm = (float*)smb;            // [128][132]
    #pragma unroll
    for (int mt = 0; mt < 2; ++mt)
        #pragma unroll
        for (int nt = 0; nt < 8; ++nt) {
            int row = wr * 32 + mt * 16 + (lane >> 2);
            int col = wn * 64 + nt * 8 + ((lane & 3) << 1);
            *(float2*)&Dsm[row * 132 + col]       = make_float2(acc[mt][nt][0], acc[mt][nt][1]);
            *(float2*)&Dsm[(row + 8) * 132 + col] = make_float2(acc[mt][nt][2], acc[mt][nt][3]);
        }
    __syncthreads();
    {
        const size_t chb = ((size_t)blockIdx.y * BB) * MD;
        #pragma unroll
        for (int i = 0; i < 8; ++i) {
            int idx = t + i * 256;
            int b = idx & 63;
            int q = idx >> 6;
            int c0 = q * 4;
            float4 v0 = *(float4*)&Dsm[b * 132 + c0];
            float4 v1 = *(float4*)&Dsm[(b + 64) * 132 + c0];
            float4 o = make_float4(fmaxf(v0.x, v1.x), fmaxf(v0.y, v1.y),
                                   fmaxf(v0.z, v1.z), fmaxf(v0.w, v1.w));
            *(float4*)&g_part[chb + (size_t)b * MD + m0 + c0] = o;
        }
    }
}

// ---------------- K4: final reduce + tanh + logits + log_softmax ------------
__global__ void head_kernel(const float* __restrict__ bmax,
                            const float* __restrict__ Wdoc,
                            const float* __restrict__ bdoc,
                            float* __restrict__ out) {
    __shared__ float ysh[MD];
    __shared__ float lsh[NC];
    const int b = blockIdx.x;
    const int t = threadIdx.x;
    for (int m = t; m < MD; m += 256) {
        float v = -3.402823466e38f;
        for (int ch = 0; ch < NCH; ++ch)
            v = fmaxf(v, g_part[((size_t)ch * BB + b) * MD + m]);
        ysh[m] = tanhf(v + bmax[m]);
    }
    __syncthreads();
    const int w = t >> 5, lane = t & 31;
    for (int c = w; c < NC; c += 8) {
        float sum = 0.f;
        for (int m = lane; m < MD; m += 32)
            sum += ysh[m] * Wdoc[(size_t)c * MD + m];
        #pragma unroll
        for (int off = 16; off; off >>= 1)
            sum += __shfl_down_sync(0xffffffffu, sum, off);
        if (lane == 0) lsh[c] = sum + bdoc[c];
    }
    __syncthreads();
    if (t == 0) {
        float mx = lsh[0];
        for (int c = 1; c < NC; ++c) mx = fmaxf(mx, lsh[c]);
        float se = 0.f;
        for (int c = 0; c < NC; ++c) se += expf(lsh[c] - mx);
        float lse = logf(se) + mx;
        for (int c = 0; c < NC; ++c) out[b * NC + c] = lsh[c] - lse;
    }
}

// ---------------- launch -----------------------------------------------------
extern "C" void kernel_launch(void* const* d_in, const int* in_sizes, int n_in,
                              void* d_out, int out_size) {
    const int*   inp   = (const int*)  d_in[0];
    const float* table = (const float*)d_in[1];
    const float* cl0   = (const float*)d_in[2];
    const float* cr0   = (const float*)d_in[3];
    const float* Wl    = (const float*)d_in[4];
    const float* bl    = (const float*)d_in[5];
    const float* Wr    = (const float*)d_in[6];
    const float* br    = (const float*)d_in[7];
    const float* Wsl   = (const float*)d_in[8];
    const float* bsl   = (const float*)d_in[9];
    const float* Wsr   = (const float*)d_in[10];
    const float* bsr   = (const float*)d_in[11];
    const float* Wmax  = (const float*)d_in[12];
    const float* bmax  = (const float*)d_in[13];
    const float* Wdoc  = (const float*)d_in[14];
    const float* bdoc  = (const float*)d_in[15];
    float* out = (float*)d_out;

    cudaFuncSetAttribute(scan_kernel,
                         cudaFuncAttributeMaxDynamicSharedMemorySize,
                         SCAN_SMEM_BYTES);
    cudaFuncSetAttribute(ymax_kernel,
                         cudaFuncAttributeMaxDynamicSharedMemorySize,
                         YM_SMEM);
    cudaFuncSetAttribute(proj_kernel,
                         cudaFuncAttributeMaxDynamicSharedMemorySize,
                         YM_SMEM);

    gather_kernel<<<NROW, 128>>>(inp, table);
    convw_kernel<<<MD, 256>>>(Wmax);
    convp_kernel<<<1024, 256>>>(Wsl, Wsr);
    proj_kernel<<<dim3(1024 / 128, NROW / 128), 256, YM_SMEM>>>(bsl, bsr);
    scan_kernel<<<128, 256, SCAN_SMEM_BYTES>>>(Wl, bl, Wr, br, cl0, cr0);
    ymax_kernel<<<dim3(MD / 128, NCH), 256, YM_SMEM>>>();
    head_kernel<<<BB, 256>>>(bmax, Wdoc, bdoc, out);
}

// round 17
// speedup vs baseline: 1.7350x; 1.6176x over previous
#include <cuda_runtime.h>
#include <cuda_bf16.h>
#include <math.h>
#include <stdint.h>

#define SS   512
#define BB   64
#define HH   512
#define EE   512
#define MD   1024
#define NC   20
#define BH   (BB*HH)     // 32768
#define NROW (SS*BB)     // 32768
#define NCH  256         // s-pair chunks in phase C

// ---------------- scratch (static device memory; no allocs) ----------------
__device__ float g_emb[(size_t)NROW*EE];
__device__ float g_els[(size_t)NROW*HH];
__device__ float g_ers[(size_t)NROW*HH];
__device__ float g_cl [(size_t)NROW*HH];
__device__ float g_cr [(size_t)NROW*HH];
__device__ float g_part[(size_t)NCH*BB*MD];
__device__ __nv_bfloat16 g_whi[(size_t)MD*1536];    // Wmax hi
__device__ __nv_bfloat16 g_wlo[(size_t)MD*1536];    // Wmax lo
__device__ __nv_bfloat16 g_pwhi[(size_t)1024*512];  // [Wsl;Wsr] hi
__device__ __nv_bfloat16 g_pwlo[(size_t)1024*512];  // [Wsl;Wsr] lo

// ---------------- helpers ----------------------------------------------------
__device__ __forceinline__ uint32_t s2u(const void* p) {
    uint32_t a;
    asm("{ .reg .u64 t; cvta.to.shared.u64 t, %1; cvt.u32.u64 %0, t; }"
        : "=r"(a) : "l"(p));
    return a;
}
#define CLUSTER_SYNC() do { \
    asm volatile("barrier.cluster.arrive.aligned;" ::: "memory"); \
    asm volatile("barrier.cluster.wait.aligned;"   ::: "memory"); } while (0)

// ---------------- warp-MMA plumbing (sm_80+ instructions) -------------------
#define LDSM4(r, addr) \
    asm volatile("ldmatrix.sync.aligned.m8n8.x4.shared.b16 {%0,%1,%2,%3}, [%4];" \
        : "=r"((r)[0]), "=r"((r)[1]), "=r"((r)[2]), "=r"((r)[3]) : "r"(addr))
#define LDSM2(r, addr) \
    asm volatile("ldmatrix.sync.aligned.m8n8.x2.shared.b16 {%0,%1}, [%2];" \
        : "=r"((r)[0]), "=r"((r)[1]) : "r"(addr))
#define MMA_BF16(d, a, b) \
    asm volatile("mma.sync.aligned.m16n8k16.row.col.f32.bf16.bf16.f32 " \
        "{%0,%1,%2,%3}, {%4,%5,%6,%7}, {%8,%9}, {%0,%1,%2,%3};" \
        : "+f"((d)[0]), "+f"((d)[1]), "+f"((d)[2]), "+f"((d)[3]) \
        : "r"((a)[0]), "r"((a)[1]), "r"((a)[2]), "r"((a)[3]), \
          "r"((b)[0]), "r"((b)[1]))

// bf16 hi/lo split of a float pair (lo residual is exact in fp32)
__device__ __forceinline__ void split2(float x, float y, uint32_t& hi, uint32_t& lo) {
    __nv_bfloat162 h2 = __floats2bfloat162_rn(x, y);
    float hx = __bfloat162float(h2.x);
    float hy = __bfloat162float(h2.y);
    __nv_bfloat162 l2 = __floats2bfloat162_rn(x - hx, y - hy);
    hi = *(uint32_t*)&h2;
    lo = *(uint32_t*)&l2;
}

// shared tile geometry for both mma kernels
#define YM_PITCH 80
#define YM_MATB  (128*YM_PITCH)          // 10240
#define YM_AHI   0
#define YM_ALO   (YM_MATB)
#define YM_BHI   (2*YM_MATB)
#define YM_BLO   (3*YM_MATB)
#define YM_BUF   (4*YM_MATB)             // 40960
#define YM_SMEM  (2*YM_BUF)              // 81920 ; x2 CTAs = 160KB <= 228KB

// ---------------- K0: embedding gather -------------------------------------
__global__ void gather_kernel(const int* __restrict__ inp,
                              const float* __restrict__ table) {
    int sb = blockIdx.x;
    int tok = inp[sb];
    const float4* src = reinterpret_cast<const float4*>(table + (size_t)tok * EE);
    float4* dst = reinterpret_cast<float4*>(g_emb + (size_t)sb * EE);
    dst[threadIdx.x] = src[threadIdx.x];
}

// ---------------- K0c: Wmax -> bf16 hi/lo -----------------------------------
__global__ void convw_kernel(const float* __restrict__ Wmax) {
    int m = blockIdx.x;
    for (int k = threadIdx.x; k < 1536; k += 256) {
        float x = Wmax[(size_t)m * 1536 + k];
        __nv_bfloat16 h = __float2bfloat16(x);
        float hf = __bfloat162float(h);
        g_whi[(size_t)m * 1536 + k] = h;
        g_wlo[(size_t)m * 1536 + k] = __float2bfloat16(x - hf);
    }
}

// ---------------- K0d: [Wsl;Wsr] -> bf16 hi/lo -------------------------------
__global__ void convp_kernel(const float* __restrict__ Wsl,
                             const float* __restrict__ Wsr) {
    int n = blockIdx.x;   // 0..1023
    const float* src = (n < 512) ? (Wsl + (size_t)n * 512)
                                 : (Wsr + (size_t)(n - 512) * 512);
    for (int k = threadIdx.x; k < 512; k += 256) {
        float x = src[k];
        __nv_bfloat16 h = __float2bfloat16(x);
        g_pwhi[(size_t)n * 512 + k] = h;
        g_pwlo[(size_t)n * 512 + k] = __float2bfloat16(x - __bfloat162float(h));
    }
}

// ---------------- K1: projection GEMM via mma.sync (hi/lo 3-term) -----------
#define PR_CH 16

__global__ __launch_bounds__(256, 2)
void proj_kernel(const float* __restrict__ bsl, const float* __restrict__ bsr) {
    extern __shared__ char smb[];
    const uint32_t sbase = s2u(smb);
    const int t = threadIdx.x;
    const int lane = t & 31, wid = t >> 5;
    const int wr = wid & 3;
    const int wn = wid >> 2;
    const int n0 = blockIdx.x * 128;
    const int r0 = blockIdx.y * 128;
    const int frow = t >> 1, fhalf = t & 1;

    float acc[2][8][4];
    #pragma unroll
    for (int i = 0; i < 2; ++i)
        #pragma unroll
        for (int j = 0; j < 8; ++j)
            #pragma unroll
            for (int k = 0; k < 4; ++k) acc[i][j][k] = 0.f;

    auto fill_buf = [&](int bufi, int ch) {
        char* dst = smb + bufi * YM_BUF;
        const float* ap = g_emb + (size_t)(r0 + frow) * 512 + ch * 32 + fhalf * 16;
        float4 f0 = *(const float4*)(ap);
        float4 f1 = *(const float4*)(ap + 4);
        float4 f2 = *(const float4*)(ap + 8);
        float4 f3 = *(const float4*)(ap + 12);
        uint32_t hv[8], lv[8];
        split2(f0.x, f0.y, hv[0], lv[0]); split2(f0.z, f0.w, hv[1], lv[1]);
        split2(f1.x, f1.y, hv[2], lv[2]); split2(f1.z, f1.w, hv[3], lv[3]);
        split2(f2.x, f2.y, hv[4], lv[4]); split2(f2.z, f2.w, hv[5], lv[5]);
        split2(f3.x, f3.y, hv[6], lv[6]); split2(f3.z, f3.w, hv[7], lv[7]);
        const uint32_t off = (uint32_t)(frow * YM_PITCH + fhalf * 32);
        *(uint4*)(dst + YM_AHI + off)      = make_uint4(hv[0], hv[1], hv[2], hv[3]);
        *(uint4*)(dst + YM_AHI + off + 16) = make_uint4(hv[4], hv[5], hv[6], hv[7]);
        *(uint4*)(dst + YM_ALO + off)      = make_uint4(lv[0], lv[1], lv[2], lv[3]);
        *(uint4*)(dst + YM_ALO + off + 16) = make_uint4(lv[4], lv[5], lv[6], lv[7]);
        const __nv_bfloat16* bh = g_pwhi + (size_t)(n0 + frow) * 512 + ch * 32 + fhalf * 16;
        const __nv_bfloat16* bl = g_pwlo + (size_t)(n0 + frow) * 512 + ch * 32 + fhalf * 16;
        *(uint4*)(dst + YM_BHI + off)      = *(const uint4*)(bh);
        *(uint4*)(dst + YM_BHI + off + 16) = *(const uint4*)(bh + 8);
        *(uint4*)(dst + YM_BLO + off)      = *(const uint4*)(bl);
        *(uint4*)(dst + YM_BLO + off + 16) = *(const uint4*)(bl + 8);
    };

    fill_buf(0, 0);
    __syncthreads();

    int buf = 0;
    for (int c = 0; c < PR_CH; ++c) {
        const uint32_t sA = sbase + buf * YM_BUF;
        const uint32_t sB = sA + YM_BHI;
        #pragma unroll
        for (int ks = 0; ks < 2; ++ks) {
            uint32_t ah[2][4], al[2][4];
            #pragma unroll
            for (int mt = 0; mt < 2; ++mt) {
                uint32_t addr = sA + (uint32_t)((wr * 32 + mt * 16 + (lane & 15)) * YM_PITCH
                                                + ks * 32 + (lane >> 4) * 16);
                LDSM4(ah[mt], addr);
                LDSM4(al[mt], addr + YM_MATB);
            }
            uint32_t bh2[8][2], bl2[8][2];
            const int l = lane & 15;
            #pragma unroll
            for (int nt = 0; nt < 8; ++nt) {
                uint32_t addr = sB + (uint32_t)((wn * 64 + nt * 8 + (l & 7)) * YM_PITCH
                                                + ks * 32 + ((l >> 3) & 1) * 16);
                LDSM2(bh2[nt], addr);
                LDSM2(bl2[nt], addr + YM_MATB);
            }
            #pragma unroll
            for (int mt = 0; mt < 2; ++mt)
                #pragma unroll
                for (int nt = 0; nt < 8; ++nt) {
                    MMA_BF16(acc[mt][nt], ah[mt], bh2[nt]);
                    MMA_BF16(acc[mt][nt], ah[mt], bl2[nt]);
                    MMA_BF16(acc[mt][nt], al[mt], bh2[nt]);
                }
        }
        if (c + 1 < PR_CH) {
            fill_buf(buf ^ 1, c + 1);
            __syncthreads();
            buf ^= 1;
        }
    }

    float* Out = (n0 < 512) ? g_els : g_ers;
    const float* bias = (n0 < 512) ? bsl : bsr;
    const int nb = n0 & 511;
    #pragma unroll
    for (int mt = 0; mt < 2; ++mt)
        #pragma unroll
        for (int nt = 0; nt < 8; ++nt) {
            int row = r0 + wr * 32 + mt * 16 + (lane >> 2);
            int col = wn * 64 + nt * 8 + ((lane & 3) << 1);
            float b0v = bias[nb + col];
            float b1v = bias[nb + col + 1];
            *(float2*)&Out[(size_t)row * 512 + nb + col] =
                make_float2(acc[mt][nt][0] + b0v, acc[mt][nt][1] + b1v);
            *(float2*)&Out[(size_t)(row + 8) * 512 + nb + col] =
                make_float2(acc[mt][nt][2] + b0v, acc[mt][nt][3] + b1v);
        }
}

// ---------------- K2: clustered scan v2 (512 thr, coalesced DSMEM push) -----
#define SCAN_W_FLT    (64*512)           // 32768
#define SCAN_C_FLT    (512*8)            // 4096 per buffer
#define SCAN_P_FLT    (16*8*68)          // 8704
#define SCAN_STG_FLT  512
#define SCAN_SMEM_FLT (SCAN_W_FLT + 2*SCAN_C_FLT + SCAN_P_FLT + SCAN_STG_FLT + 64)
#define SCAN_SMEM_BYTES (SCAN_SMEM_FLT*4)   // ~201KB

__global__ void __cluster_dims__(8, 1, 1) __launch_bounds__(512, 1)
scan_kernel(const float* __restrict__ Wl, const float* __restrict__ bl,
            const float* __restrict__ Wr, const float* __restrict__ br,
            const float* __restrict__ cl0, const float* __restrict__ cr0) {
    extern __shared__ float sm[];
    float* Wsh  = sm;                         // [512k][64j]
    float* cshA = sm + SCAN_W_FLT;            // [512][8b]
    float* cshB = cshA + SCAN_C_FLT;
    float* part = cshB + SCAN_C_FLT;          // [16kg*8b][68]
    float* cstg = part + SCAN_P_FLT;          // [64jl*8bi]
    float* bsh  = cstg + SCAN_STG_FLT;

    const int cid = blockIdx.x >> 3;
    const int rnk = blockIdx.x & 7;
    const int dir = cid & 1;
    const int b0  = (cid >> 1) * 8;
    const int j0  = rnk * 64;

    const float* W    = dir ? Wr  : Wl;
    const float* bias = dir ? br  : bl;
    const float* c0   = dir ? cr0 : cl0;
    const float* e    = dir ? g_ers : g_els;
    float* hist       = dir ? g_cr  : g_cl;

    const int t = threadIdx.x;
    for (int i = t; i < SCAN_W_FLT; i += 512) {
        int jl = i >> 9, k = i & 511;
        Wsh[k * 64 + jl] = W[(size_t)(j0 + jl) * 512 + k];
    }
    if (t < 64) bsh[t] = bias[j0 + t];
    for (int i = t; i < SCAN_C_FLT; i += 512)
        cshA[i] = c0[i >> 3];
    __syncthreads();
    CLUSTER_SYNC();

    const int kg    = t >> 5;                 // 16 k-groups of 32
    const int lane  = t & 31;
    const int jq    = lane & 15;              // j quad
    const int bq    = lane >> 4;              // b quad (0/1)
    const int kbase = kg * 32;
    const int bi    = t >> 6;                 // reducer: batch 0..7
    const int jl    = t & 63;                 // reducer: local col

    float* cur = cshA;
    float* nxt = cshB;

    for (int step = 0; step < SS; ++step) {
        const int s = dir ? (SS - 1 - step) : step;
        const size_t ebase = (size_t)s * BH;
        float e1 = __ldcg(&e[ebase + (size_t)(b0 + bi) * 512 + j0 + jl]);

        float acc[4][4];
        #pragma unroll
        for (int i = 0; i < 4; ++i)
            #pragma unroll
            for (int j = 0; j < 4; ++j) acc[i][j] = 0.f;

        const float* cp = cur + (size_t)kbase * 8 + bq * 4;
        const float* wp = Wsh + (size_t)kbase * 64 + jq * 4;
        #pragma unroll 8
        for (int k = 0; k < 32; ++k) {
            float4 c4 = *(const float4*)(cp + k * 8);
            float4 w4 = *(const float4*)(wp + k * 64);
            acc[0][0] += c4.x*w4.x; acc[0][1] += c4.x*w4.y; acc[0][2] += c4.x*w4.z; acc[0][3] += c4.x*w4.w;
            acc[1][0] += c4.y*w4.x; acc[1][1] += c4.y*w4.y; acc[1][2] += c4.y*w4.z; acc[1][3] += c4.y*w4.w;
            acc[2][0] += c4.z*w4.x; acc[2][1] += c4.z*w4.y; acc[2][2] += c4.z*w4.z; acc[2][3] += c4.z*w4.w;
            acc[3][0] += c4.w*w4.x; acc[3][1] += c4.w*w4.y; acc[3][2] += c4.w*w4.z; acc[3][3] += c4.w*w4.w;
        }
        #pragma unroll
        for (int bb = 0; bb < 4; ++bb) {
            int b = bq * 4 + bb;
            *(float4*)&part[(kg * 8 + b) * 68 + jq * 4] =
                make_float4(acc[bb][0], acc[bb][1], acc[bb][2], acc[bb][3]);
        }
        __syncthreads();

        // reduce: one output per thread (o = bi*64 + jl)
        float v = 0.f;
        #pragma unroll
        for (int g = 0; g < 16; ++g) v += part[(g * 8 + bi) * 68 + jl];
        v = tanhf(v + bsh[jl] + e1);
        hist[ebase + (size_t)(b0 + bi) * 512 + j0 + jl] = v;
        cstg[jl * 8 + bi] = v;
        __syncthreads();

        // coalesced push: consecutive lanes -> consecutive 4B in every rank
        const float pv = cstg[t];
        const uint32_t loc = s2u(nxt) + (uint32_t)((j0 * 8 + t) * 4);
        const uint32_t pvu = __float_as_uint(pv);
        #pragma unroll
        for (int rr = 0; rr < 8; ++rr) {
            uint32_t rem;
            asm("mapa.shared::cluster.u32 %0, %1, %2;" : "=r"(rem) : "r"(loc), "r"(rr));
            asm volatile("st.shared::cluster.b32 [%0], %1;" :: "r"(rem), "r"(pvu) : "memory");
        }
        CLUSTER_SYNC();
        float* tmp = cur; cur = nxt; nxt = tmp;
    }
}

// ---------------- K3: ymax via warp-level bf16 mma.sync; occupancy 2 --------
#define YM_CH    48

__global__ __launch_bounds__(256, 2)
void ymax_kernel() {
    extern __shared__ char smb[];
    const uint32_t sbase = s2u(smb);
    const int t = threadIdx.x;
    const int lane = t & 31, wid = t >> 5;
    const int wr = wid & 3;
    const int wn = wid >> 2;
    const int m0 = blockIdx.x * 128;
    const int r0 = blockIdx.y * 128;
    const int frow = t >> 1, fhalf = t & 1;

    float acc[2][8][4];
    #pragma unroll
    for (int i = 0; i < 2; ++i)
        #pragma unroll
        for (int j = 0; j < 8; ++j)
            #pragma unroll
            for (int k = 0; k < 4; ++k) acc[i][j][k] = 0.f;

    auto fill_buf = [&](int bufi, int ch) {
        char* dst = smb + bufi * YM_BUF;
        const float* Asrc = (ch < 16) ? g_cl : (ch < 32) ? g_emb : g_cr;
        const float* ap = Asrc + (size_t)(r0 + frow) * 512 + (ch & 15) * 32 + fhalf * 16;
        float4 f0 = *(const float4*)(ap);
        float4 f1 = *(const float4*)(ap + 4);
        float4 f2 = *(const float4*)(ap + 8);
        float4 f3 = *(const float4*)(ap + 12);
        uint32_t hv[8], lv[8];
        split2(f0.x, f0.y, hv[0], lv[0]); split2(f0.z, f0.w, hv[1], lv[1]);
        split2(f1.x, f1.y, hv[2], lv[2]); split2(f1.z, f1.w, hv[3], lv[3]);
        split2(f2.x, f2.y, hv[4], lv[4]); split2(f2.z, f2.w, hv[5], lv[5]);
        split2(f3.x, f3.y, hv[6], lv[6]); split2(f3.z, f3.w, hv[7], lv[7]);
        const uint32_t off = (uint32_t)(frow * YM_PITCH + fhalf * 32);
        *(uint4*)(dst + YM_AHI + off)      = make_uint4(hv[0], hv[1], hv[2], hv[3]);
        *(uint4*)(dst + YM_AHI + off + 16) = make_uint4(hv[4], hv[5], hv[6], hv[7]);
        *(uint4*)(dst + YM_ALO + off)      = make_uint4(lv[0], lv[1], lv[2], lv[3]);
        *(uint4*)(dst + YM_ALO + off + 16) = make_uint4(lv[4], lv[5], lv[6], lv[7]);
        const __nv_bfloat16* bh = g_whi + (size_t)(m0 + frow) * 1536 + ch * 32 + fhalf * 16;
        const __nv_bfloat16* bl = g_wlo + (size_t)(m0 + frow) * 1536 + ch * 32 + fhalf * 16;
        *(uint4*)(dst + YM_BHI + off)      = *(const uint4*)(bh);
        *(uint4*)(dst + YM_BHI + off + 16) = *(const uint4*)(bh + 8);
        *(uint4*)(dst + YM_BLO + off)      = *(const uint4*)(bl);
        *(uint4*)(dst + YM_BLO + off + 16) = *(const uint4*)(bl + 8);
    };

    fill_buf(0, 0);
    __syncthreads();

    int buf = 0;
    for (int c = 0; c < YM_CH; ++c) {
        const uint32_t sA = sbase + buf * YM_BUF;
        const uint32_t sB = sA + YM_BHI;
        #pragma unroll
        for (int ks = 0; ks < 2; ++ks) {
            uint32_t ah[2][4], al[2][4];
            #pragma unroll
            for (int mt = 0; mt < 2; ++mt) {
                uint32_t addr = sA + (uint32_t)((wr * 32 + mt * 16 + (lane & 15)) * YM_PITCH
                                                + ks * 32 + (lane >> 4) * 16);
                LDSM4(ah[mt], addr);
                LDSM4(al[mt], addr + YM_MATB);
            }
            uint32_t bh2[8][2], bl2[8][2];
            const int l = lane & 15;
            #pragma unroll
            for (int nt = 0; nt < 8; ++nt) {
                uint32_t addr = sB + (uint32_t)((wn * 64 + nt * 8 + (l & 7)) * YM_PITCH
                                                + ks * 32 + ((l >> 3) & 1) * 16);
                LDSM2(bh2[nt], addr);
                LDSM2(bl2[nt], addr + YM_MATB);
            }
            #pragma unroll
            for (int mt = 0; mt < 2; ++mt)
                #pragma unroll
                for (int nt = 0; nt < 8; ++nt) {
                    MMA_BF16(acc[mt][nt], ah[mt], bh2[nt]);
                    MMA_BF16(acc[mt][nt], ah[mt], bl2[nt]);
                    MMA_BF16(acc[mt][nt], al[mt], bh2[nt]);
                }
        }
        if (c + 1 < YM_CH) {
            fill_buf(buf ^ 1, c + 1);
            __syncthreads();
            buf ^= 1;
        }
    }
    __syncthreads();

    float* Dsm = (float*)smb;            // [128][132]
    #pragma unroll
    for (int mt = 0; mt < 2; ++mt)
        #pragma unroll
        for (int nt = 0; nt < 8; ++nt) {
            int row = wr * 32 + mt * 16 + (lane >> 2);
            int col = wn * 64 + nt * 8 + ((lane & 3) << 1);
            *(float2*)&Dsm[row * 132 + col]       = make_float2(acc[mt][nt][0], acc[mt][nt][1]);
            *(float2*)&Dsm[(row + 8) * 132 + col] = make_float2(acc[mt][nt][2], acc[mt][nt][3]);
        }
    __syncthreads();
    {
        const size_t chb = ((size_t)blockIdx.y * BB) * MD;
        #pragma unroll
        for (int i = 0; i < 8; ++i) {
            int idx = t + i * 256;
            int b = idx & 63;
            int q = idx >> 6;
            int c0 = q * 4;
            float4 v0 = *(float4*)&Dsm[b * 132 + c0];
            float4 v1 = *(float4*)&Dsm[(b + 64) * 132 + c0];
            float4 o = make_float4(fmaxf(v0.x, v1.x), fmaxf(v0.y, v1.y),
                                   fmaxf(v0.z, v1.z), fmaxf(v0.w, v1.w));
            *(float4*)&g_part[chb + (size_t)b * MD + m0 + c0] = o;
        }
    }
}

// ---------------- K4: final reduce + tanh + logits + log_softmax ------------
__global__ void head_kernel(const float* __restrict__ bmax,
                            const float* __restrict__ Wdoc,
                            const float* __restrict__ bdoc,
                            float* __restrict__ out) {
    __shared__ float ysh[MD];
    __shared__ float lsh[NC];
    const int b = blockIdx.x;
    const int t = threadIdx.x;
    for (int m = t; m < MD; m += 256) {
        float v = -3.402823466e38f;
        for (int ch = 0; ch < NCH; ++ch)
            v = fmaxf(v, g_part[((size_t)ch * BB + b) * MD + m]);
        ysh[m] = tanhf(v + bmax[m]);
    }
    __syncthreads();
    const int w = t >> 5, lane = t & 31;
    for (int c = w; c < NC; c += 8) {
        float sum = 0.f;
        for (int m = lane; m < MD; m += 32)
            sum += ysh[m] * Wdoc[(size_t)c * MD + m];
        #pragma unroll
        for (int off = 16; off; off >>= 1)
            sum += __shfl_down_sync(0xffffffffu, sum, off);
        if (lane == 0) lsh[c] = sum + bdoc[c];
    }
    __syncthreads();
    if (t == 0) {
        float mx = lsh[0];
        for (int c = 1; c < NC; ++c) mx = fmaxf(mx, lsh[c]);
        float se = 0.f;
        for (int c = 0; c < NC; ++c) se += expf(lsh[c] - mx);
        float lse = logf(se) + mx;
        for (int c = 0; c < NC; ++c) out[b * NC + c] = lsh[c] - lse;
    }
}

// ---------------- launch -----------------------------------------------------
extern "C" void kernel_launch(void* const* d_in, const int* in_sizes, int n_in,
                              void* d_out, int out_size) {
    const int*   inp   = (const int*)  d_in[0];
    const float* table = (const float*)d_in[1];
    const float* cl0   = (const float*)d_in[2];
    const float* cr0   = (const float*)d_in[3];
    const float* Wl    = (const float*)d_in[4];
    const float* bl    = (const float*)d_in[5];
    const float* Wr    = (const float*)d_in[6];
    const float* br    = (const float*)d_in[7];
    const float* Wsl   = (const float*)d_in[8];
    const float* bsl   = (const float*)d_in[9];
    const float* Wsr   = (const float*)d_in[10];
    const float* bsr   = (const float*)d_in[11];
    const float* Wmax  = (const float*)d_in[12];
    const float* bmax  = (const float*)d_in[13];
    const float* Wdoc  = (const float*)d_in[14];
    const float* bdoc  = (const float*)d_in[15];
    float* out = (float*)d_out;

    cudaFuncSetAttribute(scan_kernel,
                         cudaFuncAttributeMaxDynamicSharedMemorySize,
                         SCAN_SMEM_BYTES);
    cudaFuncSetAttribute(ymax_kernel,
                         cudaFuncAttributeMaxDynamicSharedMemorySize,
                         YM_SMEM);
    cudaFuncSetAttribute(proj_kernel,
                         cudaFuncAttributeMaxDynamicSharedMemorySize,
                         YM_SMEM);

    gather_kernel<<<NROW, 128>>>(inp, table);
    convw_kernel<<<MD, 256>>>(Wmax);
    convp_kernel<<<1024, 256>>>(Wsl, Wsr);
    proj_kernel<<<dim3(1024 / 128, NROW / 128), 256, YM_SMEM>>>(bsl, bsr);
    scan_kernel<<<128, 512, SCAN_SMEM_BYTES>>>(Wl, bl, Wr, br, cl0, cr0);
    ymax_kernel<<<dim3(MD / 128, NCH), 256, YM_SMEM>>>();
    head_kernel<<<BB, 256>>>(bmax, Wdoc, bdoc, out);
}